// round 15
// baseline (speedup 1.0000x reference)
#include <cuda_runtime.h>
#include <cuda_bf16.h>
#include <math.h>

// Problem constants
#define NN 40000
#define EE 640000
#define HH 128
#define GG 16
#define CC 10
#define CAP 64        // bucket capacity per node (deg ~ Poisson(16), max ~45)

// ---------------- scratch (device globals) -------------------------------------
__device__ float4 g_h4[NN * 32];    // node features, [N,128] f32
__device__ uint2  g_hwb[NN * 32];   // h @ W, [N,128] packed bf16
__device__ float  g_dis[NN];        // deg^-1/2 (incl self loop)
__device__ int    g_degc[NN];       // in-degree (atomic cursor during fill)
__device__ int    g_bucket[NN * CAP]; // adjacency buckets (src ids by dst)
__device__ float  g_w01[HH * HH];   // W_in @ W1 (fused input+conv1 weights)
__device__ float  g_b01[HH];        // b_in @ W1
__device__ float  g_sums[GG * HH];  // pooling partial sums
__device__ float  g_cnt[GG];        // pooling counts
__device__ int    g_done;           // last-block ticket for fused head

// ---------------- zero scratch ------------------------------------------------
__global__ void k_zero() {
    int i = blockIdx.x * blockDim.x + threadIdx.x;
    if (i < NN) g_degc[i] = 0;
    if (i < GG * HH) g_sums[i] = 0.0f;
    if (i < GG) g_cnt[i] = 0.0f;
    if (i == 0) g_done = 0;
}

// ---------------- one-pass bucket fill (4 edges/thread, OOB-hardened) ---------
__global__ void k_fillb(const int4* __restrict__ src4,
                        const int4* __restrict__ dst4) {
    int i = blockIdx.x * blockDim.x + threadIdx.x;
    if (i < EE / 4) {
        int4 s = src4[i];
        int4 d = dst4[i];
        int p;
        p = min(atomicAdd(&g_degc[d.x], 1), CAP - 1); g_bucket[(d.x << 6) + p] = s.x;
        p = min(atomicAdd(&g_degc[d.y], 1), CAP - 1); g_bucket[(d.y << 6) + p] = s.y;
        p = min(atomicAdd(&g_degc[d.z], 1), CAP - 1); g_bucket[(d.z << 6) + p] = s.z;
        p = min(atomicAdd(&g_degc[d.w], 1), CAP - 1); g_bucket[(d.w << 6) + p] = s.w;
    }
}

// ---------------- deg_inv_sqrt ------------------------------------------------
__global__ void k_dis() {
    int i = blockIdx.x * blockDim.x + threadIdx.x;
    if (i < NN) g_dis[i] = rsqrtf((float)g_degc[i] + 1.0f);
}

// ---------------- fused W01 = W_in@W1, b01 = b_in@W1 (k-split, low latency) ---
__global__ __launch_bounds__(512) void k_w01b(const float* __restrict__ W_in,
                                              const float* __restrict__ b_in,
                                              const float* __restrict__ W1) {
    __shared__ float arow[HH];
    __shared__ float part[HH];
    int r = blockIdx.x;
    int t = threadIdx.x;
    int c = t & 127;        // output column
    int q = t >> 7;         // k-quarter 0..3
    if (t < HH) {
        arow[t] = (r < HH) ? W_in[r * HH + t] : b_in[t];
        part[t] = 0.0f;
    }
    __syncthreads();
    int k0 = q * 32;
    float a0 = 0.f, a1 = 0.f, a2 = 0.f, a3 = 0.f;
    #pragma unroll
    for (int k = 0; k < 32; k += 4) {
        a0 = fmaf(arow[k0 + k + 0], W1[(k0 + k + 0) * HH + c], a0);
        a1 = fmaf(arow[k0 + k + 1], W1[(k0 + k + 1) * HH + c], a1);
        a2 = fmaf(arow[k0 + k + 2], W1[(k0 + k + 2) * HH + c], a2);
        a3 = fmaf(arow[k0 + k + 3], W1[(k0 + k + 3) * HH + c], a3);
    }
    atomicAdd(&part[c], (a0 + a1) + (a2 + a3));
    __syncthreads();
    if (t < HH) {
        if (r < HH) g_w01[r * HH + t] = part[t];
        else        g_b01[t] = part[t];
    }
}

// ---------------- tf32 helpers ------------------------------------------------
__device__ __forceinline__ unsigned f2tf32(float f) {
    unsigned r;
    asm("cvt.rna.tf32.f32 %0, %1;" : "=r"(r) : "f"(f));
    return r;
}

__device__ __forceinline__ void mma_tf32(float* c, unsigned a0, unsigned a1,
                                         unsigned a2, unsigned a3,
                                         unsigned b0, unsigned b1) {
    asm volatile(
        "mma.sync.aligned.m16n8k8.row.col.f32.tf32.tf32.f32 "
        "{%0,%1,%2,%3}, {%4,%5,%6,%7}, {%8,%9}, {%0,%1,%2,%3};\n"
        : "+f"(c[0]), "+f"(c[1]), "+f"(c[2]), "+f"(c[3])
        : "r"(a0), "r"(a1), "r"(a2), "r"(a3), "r"(b0), "r"(b1));
}

// ---------------- tf32 tensor-core GEMM (double-buffered) ---------------------
__global__ __launch_bounds__(256) void k_gemm_tc(const float* __restrict__ A_ext,
                                                 int a_sel, int has_bias,
                                                 int w_sel, int b_sel,
                                                 const float* __restrict__ W,
                                                 const float* __restrict__ bias) {
    const float* A = (a_sel == 0) ? A_ext : (const float*)g_h4;
    const float* Wp = (w_sel == 1) ? g_w01 : W;
    const float* bptr = (b_sel == 1) ? g_b01 : bias;

    __shared__ unsigned As[2][64][36];
    __shared__ unsigned Bs[2][32][136];

    int t = threadIdx.x;
    int lane = t & 31;
    int wid = t >> 5;
    int g = lane >> 2, tg = lane & 3;
    int m0 = (wid >> 2) * 32;
    int n0 = (wid & 3) * 32;
    int rowBase = blockIdx.x * 64;

    int ar = t >> 3, ac4 = (t & 7) * 4;
    int br = t >> 5, bc4 = (t & 31) * 4;

    float acc[2][4][4];
    #pragma unroll
    for (int mi = 0; mi < 2; mi++)
        #pragma unroll
        for (int ni = 0; ni < 4; ni++)
            #pragma unroll
            for (int q = 0; q < 4; q++) acc[mi][ni][q] = 0.0f;

    {
        #pragma unroll
        for (int i = 0; i < 2; i++) {
            int r = ar + i * 32;
            float4 v = *(const float4*)&A[(size_t)(rowBase + r) * 128 + ac4];
            uint4 u; u.x = f2tf32(v.x); u.y = f2tf32(v.y); u.z = f2tf32(v.z); u.w = f2tf32(v.w);
            *(uint4*)&As[0][r][ac4] = u;
        }
        #pragma unroll
        for (int i = 0; i < 4; i++) {
            int r = br + i * 8;
            float4 v = *(const float4*)&Wp[(size_t)r * 128 + bc4];
            uint4 u; u.x = f2tf32(v.x); u.y = f2tf32(v.y); u.z = f2tf32(v.z); u.w = f2tf32(v.w);
            *(uint4*)&Bs[0][r][bc4] = u;
        }
    }
    __syncthreads();

    #pragma unroll
    for (int kt = 0; kt < 4; kt++) {
        int cur = kt & 1;
        float4 pa[2], pb[4];
        if (kt < 3) {
            int k0 = (kt + 1) * 32;
            #pragma unroll
            for (int i = 0; i < 2; i++)
                pa[i] = *(const float4*)&A[(size_t)(rowBase + ar + i * 32) * 128 + k0 + ac4];
            #pragma unroll
            for (int i = 0; i < 4; i++)
                pb[i] = *(const float4*)&Wp[(size_t)(k0 + br + i * 8) * 128 + bc4];
        }

        #pragma unroll
        for (int ks = 0; ks < 4; ks++) {
            int kk = ks * 8;
            unsigned a[2][4];
            #pragma unroll
            for (int mi = 0; mi < 2; mi++) {
                int rm = m0 + mi * 16;
                a[mi][0] = As[cur][rm + g][kk + tg];
                a[mi][1] = As[cur][rm + g + 8][kk + tg];
                a[mi][2] = As[cur][rm + g][kk + tg + 4];
                a[mi][3] = As[cur][rm + g + 8][kk + tg + 4];
            }
            #pragma unroll
            for (int ni = 0; ni < 4; ni++) {
                int nb = n0 + ni * 8;
                unsigned b0 = Bs[cur][kk + tg][nb + g];
                unsigned b1 = Bs[cur][kk + tg + 4][nb + g];
                #pragma unroll
                for (int mi = 0; mi < 2; mi++)
                    mma_tf32(acc[mi][ni], a[mi][0], a[mi][1], a[mi][2], a[mi][3], b0, b1);
            }
        }

        if (kt < 3) {
            int nxt = (kt + 1) & 1;
            #pragma unroll
            for (int i = 0; i < 2; i++) {
                uint4 u; u.x = f2tf32(pa[i].x); u.y = f2tf32(pa[i].y);
                u.z = f2tf32(pa[i].z); u.w = f2tf32(pa[i].w);
                *(uint4*)&As[nxt][ar + i * 32][ac4] = u;
            }
            #pragma unroll
            for (int i = 0; i < 4; i++) {
                uint4 u; u.x = f2tf32(pb[i].x); u.y = f2tf32(pb[i].y);
                u.z = f2tf32(pb[i].z); u.w = f2tf32(pb[i].w);
                *(uint4*)&Bs[nxt][br + i * 8][bc4] = u;
            }
            __syncthreads();
        }
    }

    unsigned* Cb = (unsigned*)g_hwb;
    #pragma unroll
    for (int ni = 0; ni < 4; ni++) {
        int col = n0 + ni * 8 + 2 * tg;
        float bv0 = 0.f, bv1 = 0.f;
        if (has_bias) { bv0 = bptr[col]; bv1 = bptr[col + 1]; }
        #pragma unroll
        for (int mi = 0; mi < 2; mi++) {
            int r0 = rowBase + m0 + mi * 16 + g;
            int r1 = r0 + 8;
            __nv_bfloat162 p0, p1;
            p0.x = __float2bfloat16(acc[mi][ni][0] + bv0);
            p0.y = __float2bfloat16(acc[mi][ni][1] + bv1);
            p1.x = __float2bfloat16(acc[mi][ni][2] + bv0);
            p1.y = __float2bfloat16(acc[mi][ni][3] + bv1);
            Cb[(size_t)r0 * 64 + (col >> 1)] = *(unsigned*)&p0;
            Cb[(size_t)r1 * 64 + (col >> 1)] = *(unsigned*)&p1;
        }
    }
}

// ---------------- GCN aggregation (+fused pool & head on last block) ----------
// 8-way predicated unroll: no serial remainder, 8 gathers in flight per warp.
__device__ __forceinline__ void bf16x4_fma(float4& acc, float w, uint2 u) {
    float2 f0 = __bfloat1622float2(*(__nv_bfloat162*)&u.x);
    float2 f1 = __bfloat1622float2(*(__nv_bfloat162*)&u.y);
    acc.x = fmaf(w, f0.x, acc.x);
    acc.y = fmaf(w, f0.y, acc.y);
    acc.z = fmaf(w, f1.x, acc.z);
    acc.w = fmaf(w, f1.y, acc.w);
}

__global__ __launch_bounds__(256) void k_agg(const float* __restrict__ bias,
                                             const int* __restrict__ batch,
                                             int do_pool,
                                             const float* __restrict__ Wf1,
                                             const float* __restrict__ bf1,
                                             const float* __restrict__ Wf2,
                                             const float* __restrict__ bf2,
                                             float* __restrict__ out) {
    __shared__ float sacc[2][HH];
    __shared__ float scnt[2];
    __shared__ int   sg[2];
    __shared__ int   sticket;

    int tid = threadIdx.x;
    int warp = (blockIdx.x << 3) + (tid >> 5);
    int lane = tid & 31;
    int node0 = blockIdx.x << 3;

    if (do_pool) {
        if (tid == 0) { sg[0] = batch[node0]; sg[1] = batch[node0 + 7]; }
        if (tid < 2) scnt[tid] = 0.0f;
        if (tid < 128) sacc[0][tid] = 0.0f; else sacc[1][tid - 128] = 0.0f;
        __syncthreads();
    }

    float dn = g_dis[warp];
    int deg = min(g_degc[warp], CAP);
    int base = warp << 6;
    float4 acc0 = make_float4(0.f, 0.f, 0.f, 0.f);
    float4 acc1 = make_float4(0.f, 0.f, 0.f, 0.f);
    float4 acc2 = make_float4(0.f, 0.f, 0.f, 0.f);
    float4 acc3 = make_float4(0.f, 0.f, 0.f, 0.f);

    for (int e0 = 0; e0 < deg; e0 += 8) {
        int s[8]; float w[8]; uint2 u[8];
        #pragma unroll
        for (int j = 0; j < 8; j++) {
            int idx = e0 + j;
            bool v = (idx < deg);
            s[j] = v ? g_bucket[base + idx] : warp;   // safe dummy address
            w[j] = v ? g_dis[s[j]] * dn : 0.0f;
        }
        #pragma unroll
        for (int j = 0; j < 8; j++)
            u[j] = g_hwb[(size_t)s[j] * 32 + lane];
        bf16x4_fma(acc0, w[0], u[0]);
        bf16x4_fma(acc1, w[1], u[1]);
        bf16x4_fma(acc2, w[2], u[2]);
        bf16x4_fma(acc3, w[3], u[3]);
        bf16x4_fma(acc0, w[4], u[4]);
        bf16x4_fma(acc1, w[5], u[5]);
        bf16x4_fma(acc2, w[6], u[6]);
        bf16x4_fma(acc3, w[7], u[7]);
    }
    // self loop
    {
        float w = dn * dn;
        uint2 u = g_hwb[(size_t)warp * 32 + lane];
        bf16x4_fma(acc1, w, u);
    }
    float4 acc;
    acc.x = (acc0.x + acc1.x) + (acc2.x + acc3.x);
    acc.y = (acc0.y + acc1.y) + (acc2.y + acc3.y);
    acc.z = (acc0.z + acc1.z) + (acc2.z + acc3.z);
    acc.w = (acc0.w + acc1.w) + (acc2.w + acc3.w);
    float bb0 = bias[lane * 4 + 0];
    float bb1 = bias[lane * 4 + 1];
    float bb2 = bias[lane * 4 + 2];
    float bb3 = bias[lane * 4 + 3];
    float4 o;
    o.x = fmaxf(acc.x + bb0, 0.f);
    o.y = fmaxf(acc.y + bb1, 0.f);
    o.z = fmaxf(acc.z + bb2, 0.f);
    o.w = fmaxf(acc.w + bb3, 0.f);
    g_h4[(size_t)warp * 32 + lane] = o;

    if (!do_pool) return;

    // block-local pool (batch sorted => <=2 graphs/block)
    int slot = (batch[warp] == sg[0]) ? 0 : 1;
    atomicAdd(&sacc[slot][lane * 4 + 0], o.x);
    atomicAdd(&sacc[slot][lane * 4 + 1], o.y);
    atomicAdd(&sacc[slot][lane * 4 + 2], o.z);
    atomicAdd(&sacc[slot][lane * 4 + 3], o.w);
    if (lane == 0) atomicAdd(&scnt[slot], 1.0f);
    __syncthreads();
    int s = tid >> 7, col = tid & 127;
    bool two = (sg[1] != sg[0]);
    if (s == 0 || two) {
        atomicAdd(&g_sums[sg[s] * HH + col], sacc[s][col]);
        if (col == 0) atomicAdd(&g_cnt[sg[s]], scnt[s]);
    }

    // last-block ticket -> run MLP head inline (non-blocking pattern)
    __threadfence();
    __syncthreads();
    if (tid == 0) sticket = atomicAdd(&g_done, 1);
    __syncthreads();
    if (sticket != (NN / 8) - 1) return;

    __shared__ float pooled[GG * HH];
    __shared__ float t1[GG * 64];
    for (int i = tid; i < GG * HH; i += 256) {
        int g = i >> 7;
        float c = fmaxf(__ldcg(&g_cnt[g]), 1.0f);
        pooled[i] = __ldcg(&g_sums[i]) / c;
    }
    __syncthreads();
    for (int i = tid; i < GG * 64; i += 256) {
        int g = i >> 6, j = i & 63;
        float v = bf1[j];
        #pragma unroll 8
        for (int k = 0; k < 128; k++) v = fmaf(pooled[g * 128 + k], Wf1[k * 64 + j], v);
        t1[i] = fmaxf(v, 0.0f);
    }
    __syncthreads();
    for (int i = tid; i < GG * CC; i += 256) {
        int g = i / CC, c = i % CC;
        float v = bf2[c];
        #pragma unroll 8
        for (int k = 0; k < 64; k++) v = fmaf(t1[g * 64 + k], Wf2[k * CC + c], v);
        out[i] = v;
    }
}

// ---------------- launch (fork/join: bucket CSR || fused GEMM chain) ----------
extern "C" void kernel_launch(void* const* d_in, const int* in_sizes, int n_in,
                              void* d_out, int out_size) {
    const float* x    = (const float*)d_in[0];
    const int*   ei   = (const int*)d_in[1];   // [2, E] int32
    const int*   batch= (const int*)d_in[2];   // [N] int32
    const float* W_in = (const float*)d_in[3];
    const float* b_in = (const float*)d_in[4];
    const float* W1   = (const float*)d_in[5];
    const float* b1   = (const float*)d_in[6];
    const float* W2   = (const float*)d_in[7];
    const float* b2   = (const float*)d_in[8];
    const float* Wf1  = (const float*)d_in[9];
    const float* bf1  = (const float*)d_in[10];
    const float* Wf2  = (const float*)d_in[11];
    const float* bf2  = (const float*)d_in[12];
    float* out = (float*)d_out;

    const int4* src4 = (const int4*)ei;
    const int4* dst4 = (const int4*)(ei + EE);

    cudaStream_t s2;
    cudaStreamCreateWithFlags(&s2, cudaStreamNonBlocking);
    cudaEvent_t evFork, evJoin;
    cudaEventCreateWithFlags(&evFork, cudaEventDisableTiming);
    cudaEventCreateWithFlags(&evJoin, cudaEventDisableTiming);

    cudaEventRecord(evFork, 0);
    cudaStreamWaitEvent(s2, evFork, 0);

    // stream s2: bucket CSR build (zero -> fill -> dis)
    k_zero<<<(NN + 255) / 256, 256, 0, s2>>>();
    k_fillb<<<(EE / 4 + 255) / 256, 256, 0, s2>>>(src4, dst4);
    k_dis<<<(NN + 255) / 256, 256, 0, s2>>>();
    cudaEventRecord(evJoin, s2);

    // stream 0: W01/b01, then hw1 = x @ W01 + b01 (bf16 out)
    k_w01b<<<HH + 1, 512>>>(W_in, b_in, W1);
    k_gemm_tc<<<NN / 64, 256>>>(x, 0, 1, 1, 1, W1, b_in);

    cudaStreamWaitEvent(0, evJoin, 0);
    k_agg<<<NN / 8, 256>>>(b1, batch, 0, Wf1, bf1, Wf2, bf2, out);
    // conv2 (+ fused mean pool + fused head on last block)
    k_gemm_tc<<<NN / 64, 256>>>(x, 1, 0, 0, 0, W2, b_in);
    k_agg<<<NN / 8, 256>>>(b2, batch, 1, Wf1, bf1, Wf2, bf2, out);
}

// round 17
// speedup vs baseline: 1.2454x; 1.2454x over previous
#include <cuda_runtime.h>
#include <cuda_bf16.h>
#include <math.h>

// Problem constants
#define NN 40000
#define EE 640000
#define HH 128
#define GG 16
#define CC 10
#define CAP 64        // bucket capacity per node (deg ~ Poisson(16), max ~45)

// ---------------- scratch (device globals) -------------------------------------
__device__ float4 g_h4[NN * 32];    // node features, [N,128] f32
__device__ uint2  g_hwb[NN * 32];   // h @ W, [N,128] packed bf16
__device__ float  g_dis[NN];        // deg^-1/2 (incl self loop)
__device__ int    g_degc[NN];       // in-degree (atomic cursor during fill)
__device__ int    g_bucket[NN * CAP]; // adjacency buckets (src ids by dst)
__device__ float  g_w01[HH * HH];   // W_in @ W1 (fused input+conv1 weights)
__device__ float  g_b01[HH];        // b_in @ W1
__device__ float  g_sums[GG * HH];  // pooling partial sums
__device__ float  g_cnt[GG];        // pooling counts
__device__ int    g_done;           // last-block ticket for fused head

// ---------------- zero scratch ------------------------------------------------
__global__ void k_zero() {
    int i = blockIdx.x * blockDim.x + threadIdx.x;
    if (i < NN) g_degc[i] = 0;
    if (i < GG * HH) g_sums[i] = 0.0f;
    if (i < GG) g_cnt[i] = 0.0f;
    if (i == 0) g_done = 0;
}

// ---------------- one-pass bucket fill (4 edges/thread, OOB-hardened) ---------
__global__ void k_fillb(const int4* __restrict__ src4,
                        const int4* __restrict__ dst4) {
    int i = blockIdx.x * blockDim.x + threadIdx.x;
    if (i < EE / 4) {
        int4 s = src4[i];
        int4 d = dst4[i];
        int p;
        p = min(atomicAdd(&g_degc[d.x], 1), CAP - 1); g_bucket[(d.x << 6) + p] = s.x;
        p = min(atomicAdd(&g_degc[d.y], 1), CAP - 1); g_bucket[(d.y << 6) + p] = s.y;
        p = min(atomicAdd(&g_degc[d.z], 1), CAP - 1); g_bucket[(d.z << 6) + p] = s.z;
        p = min(atomicAdd(&g_degc[d.w], 1), CAP - 1); g_bucket[(d.w << 6) + p] = s.w;
    }
}

// ---------------- deg_inv_sqrt ------------------------------------------------
__global__ void k_dis() {
    int i = blockIdx.x * blockDim.x + threadIdx.x;
    if (i < NN) g_dis[i] = rsqrtf((float)g_degc[i] + 1.0f);
}

// ---------------- fused W01 = W_in@W1, b01 = b_in@W1 (k-split, low latency) ---
__global__ __launch_bounds__(512) void k_w01b(const float* __restrict__ W_in,
                                              const float* __restrict__ b_in,
                                              const float* __restrict__ W1) {
    __shared__ float arow[HH];
    __shared__ float part[HH];
    int r = blockIdx.x;
    int t = threadIdx.x;
    int c = t & 127;        // output column
    int q = t >> 7;         // k-quarter 0..3
    if (t < HH) {
        arow[t] = (r < HH) ? W_in[r * HH + t] : b_in[t];
        part[t] = 0.0f;
    }
    __syncthreads();
    int k0 = q * 32;
    float a0 = 0.f, a1 = 0.f, a2 = 0.f, a3 = 0.f;
    #pragma unroll
    for (int k = 0; k < 32; k += 4) {
        a0 = fmaf(arow[k0 + k + 0], W1[(k0 + k + 0) * HH + c], a0);
        a1 = fmaf(arow[k0 + k + 1], W1[(k0 + k + 1) * HH + c], a1);
        a2 = fmaf(arow[k0 + k + 2], W1[(k0 + k + 2) * HH + c], a2);
        a3 = fmaf(arow[k0 + k + 3], W1[(k0 + k + 3) * HH + c], a3);
    }
    atomicAdd(&part[c], (a0 + a1) + (a2 + a3));
    __syncthreads();
    if (t < HH) {
        if (r < HH) g_w01[r * HH + t] = part[t];
        else        g_b01[t] = part[t];
    }
}

// ---------------- tf32 helpers ------------------------------------------------
__device__ __forceinline__ unsigned f2tf32(float f) {
    unsigned r;
    asm("cvt.rna.tf32.f32 %0, %1;" : "=r"(r) : "f"(f));
    return r;
}

__device__ __forceinline__ void mma_tf32(float* c, unsigned a0, unsigned a1,
                                         unsigned a2, unsigned a3,
                                         unsigned b0, unsigned b1) {
    asm volatile(
        "mma.sync.aligned.m16n8k8.row.col.f32.tf32.tf32.f32 "
        "{%0,%1,%2,%3}, {%4,%5,%6,%7}, {%8,%9}, {%0,%1,%2,%3};\n"
        : "+f"(c[0]), "+f"(c[1]), "+f"(c[2]), "+f"(c[3])
        : "r"(a0), "r"(a1), "r"(a2), "r"(a3), "r"(b0), "r"(b1));
}

// ---------------- tf32 tensor-core GEMM (double-buffered) ---------------------
__global__ __launch_bounds__(256) void k_gemm_tc(const float* __restrict__ A_ext,
                                                 int a_sel, int has_bias,
                                                 int w_sel, int b_sel,
                                                 const float* __restrict__ W,
                                                 const float* __restrict__ bias) {
    const float* A = (a_sel == 0) ? A_ext : (const float*)g_h4;
    const float* Wp = (w_sel == 1) ? g_w01 : W;
    const float* bptr = (b_sel == 1) ? g_b01 : bias;

    __shared__ unsigned As[2][64][36];
    __shared__ unsigned Bs[2][32][136];

    int t = threadIdx.x;
    int lane = t & 31;
    int wid = t >> 5;
    int g = lane >> 2, tg = lane & 3;
    int m0 = (wid >> 2) * 32;
    int n0 = (wid & 3) * 32;
    int rowBase = blockIdx.x * 64;

    int ar = t >> 3, ac4 = (t & 7) * 4;
    int br = t >> 5, bc4 = (t & 31) * 4;

    float acc[2][4][4];
    #pragma unroll
    for (int mi = 0; mi < 2; mi++)
        #pragma unroll
        for (int ni = 0; ni < 4; ni++)
            #pragma unroll
            for (int q = 0; q < 4; q++) acc[mi][ni][q] = 0.0f;

    {
        #pragma unroll
        for (int i = 0; i < 2; i++) {
            int r = ar + i * 32;
            float4 v = *(const float4*)&A[(size_t)(rowBase + r) * 128 + ac4];
            uint4 u; u.x = f2tf32(v.x); u.y = f2tf32(v.y); u.z = f2tf32(v.z); u.w = f2tf32(v.w);
            *(uint4*)&As[0][r][ac4] = u;
        }
        #pragma unroll
        for (int i = 0; i < 4; i++) {
            int r = br + i * 8;
            float4 v = *(const float4*)&Wp[(size_t)r * 128 + bc4];
            uint4 u; u.x = f2tf32(v.x); u.y = f2tf32(v.y); u.z = f2tf32(v.z); u.w = f2tf32(v.w);
            *(uint4*)&Bs[0][r][bc4] = u;
        }
    }
    __syncthreads();

    #pragma unroll
    for (int kt = 0; kt < 4; kt++) {
        int cur = kt & 1;
        float4 pa[2], pb[4];
        if (kt < 3) {
            int k0 = (kt + 1) * 32;
            #pragma unroll
            for (int i = 0; i < 2; i++)
                pa[i] = *(const float4*)&A[(size_t)(rowBase + ar + i * 32) * 128 + k0 + ac4];
            #pragma unroll
            for (int i = 0; i < 4; i++)
                pb[i] = *(const float4*)&Wp[(size_t)(k0 + br + i * 8) * 128 + bc4];
        }

        #pragma unroll
        for (int ks = 0; ks < 4; ks++) {
            int kk = ks * 8;
            unsigned a[2][4];
            #pragma unroll
            for (int mi = 0; mi < 2; mi++) {
                int rm = m0 + mi * 16;
                a[mi][0] = As[cur][rm + g][kk + tg];
                a[mi][1] = As[cur][rm + g + 8][kk + tg];
                a[mi][2] = As[cur][rm + g][kk + tg + 4];
                a[mi][3] = As[cur][rm + g + 8][kk + tg + 4];
            }
            #pragma unroll
            for (int ni = 0; ni < 4; ni++) {
                int nb = n0 + ni * 8;
                unsigned b0 = Bs[cur][kk + tg][nb + g];
                unsigned b1 = Bs[cur][kk + tg + 4][nb + g];
                #pragma unroll
                for (int mi = 0; mi < 2; mi++)
                    mma_tf32(acc[mi][ni], a[mi][0], a[mi][1], a[mi][2], a[mi][3], b0, b1);
            }
        }

        if (kt < 3) {
            int nxt = (kt + 1) & 1;
            #pragma unroll
            for (int i = 0; i < 2; i++) {
                uint4 u; u.x = f2tf32(pa[i].x); u.y = f2tf32(pa[i].y);
                u.z = f2tf32(pa[i].z); u.w = f2tf32(pa[i].w);
                *(uint4*)&As[nxt][ar + i * 32][ac4] = u;
            }
            #pragma unroll
            for (int i = 0; i < 4; i++) {
                uint4 u; u.x = f2tf32(pb[i].x); u.y = f2tf32(pb[i].y);
                u.z = f2tf32(pb[i].z); u.w = f2tf32(pb[i].w);
                *(uint4*)&Bs[nxt][br + i * 8][bc4] = u;
            }
            __syncthreads();
        }
    }

    unsigned* Cb = (unsigned*)g_hwb;
    #pragma unroll
    for (int ni = 0; ni < 4; ni++) {
        int col = n0 + ni * 8 + 2 * tg;
        float bv0 = 0.f, bv1 = 0.f;
        if (has_bias) { bv0 = bptr[col]; bv1 = bptr[col + 1]; }
        #pragma unroll
        for (int mi = 0; mi < 2; mi++) {
            int r0 = rowBase + m0 + mi * 16 + g;
            int r1 = r0 + 8;
            __nv_bfloat162 p0, p1;
            p0.x = __float2bfloat16(acc[mi][ni][0] + bv0);
            p0.y = __float2bfloat16(acc[mi][ni][1] + bv1);
            p1.x = __float2bfloat16(acc[mi][ni][2] + bv0);
            p1.y = __float2bfloat16(acc[mi][ni][3] + bv1);
            Cb[(size_t)r0 * 64 + (col >> 1)] = *(unsigned*)&p0;
            Cb[(size_t)r1 * 64 + (col >> 1)] = *(unsigned*)&p1;
        }
    }
}

// ---------------- GCN aggregation (+fused pool & head on last block) ----------
// 4-wide predicated gather loop: no serial remainder, same register budget as
// the plain 4-way unroll (R14) — occupancy preserved.
__device__ __forceinline__ void bf16x4_fma(float4& acc, float w, uint2 u) {
    float2 f0 = __bfloat1622float2(*(__nv_bfloat162*)&u.x);
    float2 f1 = __bfloat1622float2(*(__nv_bfloat162*)&u.y);
    acc.x = fmaf(w, f0.x, acc.x);
    acc.y = fmaf(w, f0.y, acc.y);
    acc.z = fmaf(w, f1.x, acc.z);
    acc.w = fmaf(w, f1.y, acc.w);
}

__global__ __launch_bounds__(256) void k_agg(const float* __restrict__ bias,
                                             const int* __restrict__ batch,
                                             int do_pool,
                                             const float* __restrict__ Wf1,
                                             const float* __restrict__ bf1,
                                             const float* __restrict__ Wf2,
                                             const float* __restrict__ bf2,
                                             float* __restrict__ out) {
    __shared__ float sacc[2][HH];
    __shared__ float scnt[2];
    __shared__ int   sg[2];
    __shared__ int   sticket;

    int tid = threadIdx.x;
    int warp = (blockIdx.x << 3) + (tid >> 5);
    int lane = tid & 31;
    int node0 = blockIdx.x << 3;

    if (do_pool) {
        if (tid == 0) { sg[0] = batch[node0]; sg[1] = batch[node0 + 7]; }
        if (tid < 2) scnt[tid] = 0.0f;
        if (tid < 128) sacc[0][tid] = 0.0f; else sacc[1][tid - 128] = 0.0f;
        __syncthreads();
    }

    float dn = g_dis[warp];
    int deg = min(g_degc[warp], CAP);
    int base = warp << 6;
    float4 acc0 = make_float4(0.f, 0.f, 0.f, 0.f);
    float4 acc1 = make_float4(0.f, 0.f, 0.f, 0.f);
    float4 acc2 = make_float4(0.f, 0.f, 0.f, 0.f);
    float4 acc3 = make_float4(0.f, 0.f, 0.f, 0.f);

    for (int e0 = 0; e0 < deg; e0 += 4) {
        int s0 = (e0 + 0 < deg) ? g_bucket[base + e0 + 0] : warp;
        int s1 = (e0 + 1 < deg) ? g_bucket[base + e0 + 1] : warp;
        int s2 = (e0 + 2 < deg) ? g_bucket[base + e0 + 2] : warp;
        int s3 = (e0 + 3 < deg) ? g_bucket[base + e0 + 3] : warp;
        float w0 = (e0 + 0 < deg) ? g_dis[s0] * dn : 0.0f;
        float w1 = (e0 + 1 < deg) ? g_dis[s1] * dn : 0.0f;
        float w2 = (e0 + 2 < deg) ? g_dis[s2] * dn : 0.0f;
        float w3 = (e0 + 3 < deg) ? g_dis[s3] * dn : 0.0f;
        uint2 u0 = g_hwb[(size_t)s0 * 32 + lane];
        uint2 u1 = g_hwb[(size_t)s1 * 32 + lane];
        uint2 u2 = g_hwb[(size_t)s2 * 32 + lane];
        uint2 u3 = g_hwb[(size_t)s3 * 32 + lane];
        bf16x4_fma(acc0, w0, u0);
        bf16x4_fma(acc1, w1, u1);
        bf16x4_fma(acc2, w2, u2);
        bf16x4_fma(acc3, w3, u3);
    }
    // self loop
    {
        float w = dn * dn;
        uint2 u = g_hwb[(size_t)warp * 32 + lane];
        bf16x4_fma(acc1, w, u);
    }
    float4 acc;
    acc.x = (acc0.x + acc1.x) + (acc2.x + acc3.x);
    acc.y = (acc0.y + acc1.y) + (acc2.y + acc3.y);
    acc.z = (acc0.z + acc1.z) + (acc2.z + acc3.z);
    acc.w = (acc0.w + acc1.w) + (acc2.w + acc3.w);
    float bb0 = bias[lane * 4 + 0];
    float bb1 = bias[lane * 4 + 1];
    float bb2 = bias[lane * 4 + 2];
    float bb3 = bias[lane * 4 + 3];
    float4 o;
    o.x = fmaxf(acc.x + bb0, 0.f);
    o.y = fmaxf(acc.y + bb1, 0.f);
    o.z = fmaxf(acc.z + bb2, 0.f);
    o.w = fmaxf(acc.w + bb3, 0.f);
    g_h4[(size_t)warp * 32 + lane] = o;

    if (!do_pool) return;

    // block-local pool (batch sorted => <=2 graphs/block)
    int slot = (batch[warp] == sg[0]) ? 0 : 1;
    atomicAdd(&sacc[slot][lane * 4 + 0], o.x);
    atomicAdd(&sacc[slot][lane * 4 + 1], o.y);
    atomicAdd(&sacc[slot][lane * 4 + 2], o.z);
    atomicAdd(&sacc[slot][lane * 4 + 3], o.w);
    if (lane == 0) atomicAdd(&scnt[slot], 1.0f);
    __syncthreads();
    int s = tid >> 7, col = tid & 127;
    bool two = (sg[1] != sg[0]);
    if (s == 0 || two) {
        atomicAdd(&g_sums[sg[s] * HH + col], sacc[s][col]);
        if (col == 0) atomicAdd(&g_cnt[sg[s]], scnt[s]);
    }

    // last-block ticket -> run MLP head inline (non-blocking pattern)
    __threadfence();
    __syncthreads();
    if (tid == 0) sticket = atomicAdd(&g_done, 1);
    __syncthreads();
    if (sticket != (NN / 8) - 1) return;

    __shared__ float pooled[GG * HH];
    __shared__ float t1[GG * 64];
    for (int i = tid; i < GG * HH; i += 256) {
        int g = i >> 7;
        float c = fmaxf(__ldcg(&g_cnt[g]), 1.0f);
        pooled[i] = __ldcg(&g_sums[i]) / c;
    }
    __syncthreads();
    for (int i = tid; i < GG * 64; i += 256) {
        int g = i >> 6, j = i & 63;
        float v = bf1[j];
        #pragma unroll 8
        for (int k = 0; k < 128; k++) v = fmaf(pooled[g * 128 + k], Wf1[k * 64 + j], v);
        t1[i] = fmaxf(v, 0.0f);
    }
    __syncthreads();
    for (int i = tid; i < GG * CC; i += 256) {
        int g = i / CC, c = i % CC;
        float v = bf2[c];
        #pragma unroll 8
        for (int k = 0; k < 64; k++) v = fmaf(t1[g * 64 + k], Wf2[k * CC + c], v);
        out[i] = v;
    }
}

// ---------------- launch (fork/join: bucket CSR || fused GEMM chain) ----------
extern "C" void kernel_launch(void* const* d_in, const int* in_sizes, int n_in,
                              void* d_out, int out_size) {
    const float* x    = (const float*)d_in[0];
    const int*   ei   = (const int*)d_in[1];   // [2, E] int32
    const int*   batch= (const int*)d_in[2];   // [N] int32
    const float* W_in = (const float*)d_in[3];
    const float* b_in = (const float*)d_in[4];
    const float* W1   = (const float*)d_in[5];
    const float* b1   = (const float*)d_in[6];
    const float* W2   = (const float*)d_in[7];
    const float* b2   = (const float*)d_in[8];
    const float* Wf1  = (const float*)d_in[9];
    const float* bf1  = (const float*)d_in[10];
    const float* Wf2  = (const float*)d_in[11];
    const float* bf2  = (const float*)d_in[12];
    float* out = (float*)d_out;

    const int4* src4 = (const int4*)ei;
    const int4* dst4 = (const int4*)(ei + EE);

    cudaStream_t s2;
    cudaStreamCreateWithFlags(&s2, cudaStreamNonBlocking);
    cudaEvent_t evFork, evJoin;
    cudaEventCreateWithFlags(&evFork, cudaEventDisableTiming);
    cudaEventCreateWithFlags(&evJoin, cudaEventDisableTiming);

    cudaEventRecord(evFork, 0);
    cudaStreamWaitEvent(s2, evFork, 0);

    // stream s2: bucket CSR build (zero -> fill -> dis)
    k_zero<<<(NN + 255) / 256, 256, 0, s2>>>();
    k_fillb<<<(EE / 4 + 255) / 256, 256, 0, s2>>>(src4, dst4);
    k_dis<<<(NN + 255) / 256, 256, 0, s2>>>();
    cudaEventRecord(evJoin, s2);

    // stream 0: W01/b01, then hw1 = x @ W01 + b01 (bf16 out)
    k_w01b<<<HH + 1, 512>>>(W_in, b_in, W1);
    k_gemm_tc<<<NN / 64, 256>>>(x, 0, 1, 1, 1, W1, b_in);

    cudaStreamWaitEvent(0, evJoin, 0);
    k_agg<<<NN / 8, 256>>>(b1, batch, 0, Wf1, bf1, Wf2, bf2, out);
    // conv2 (+ fused mean pool + fused head on last block)
    k_gemm_tc<<<NN / 64, 256>>>(x, 1, 0, 0, 0, W2, b_in);
    k_agg<<<NN / 8, 256>>>(b2, batch, 1, Wf1, bf1, Wf2, bf2, out);
}